// round 1
// baseline (speedup 1.0000x reference)
#include <cuda_runtime.h>

#define BWIN 4096
#define NTOK 49
#define DIM  256
#define NH   8
#define HD   32
#define QKV_S (BWIN * NH * NTOK * HD)   /* 51,380,224 elems per q/k/v */

// Scratch (device globals: allocation-free per harness rules)
__device__ float g_qkv[3ULL * QKV_S];                        // [3][B][H][N][hd]
__device__ float g_att[(size_t)BWIN * NTOK * DIM];           // [B*N][C], C = h*32+d
__device__ float g_bias[NH * NTOK * NTOK];                   // [H][N][N]

typedef unsigned long long u64;

__device__ __forceinline__ u64 f2fma(u64 a, u64 b, u64 c) {
    u64 d;
    asm("fma.rn.f32x2 %0, %1, %2, %3;" : "=l"(d) : "l"(a), "l"(b), "l"(c));
    return d;
}

// ---------------------------------------------------------------------------
// Kernel 0: build relative-position bias [H][N][N]
// ---------------------------------------------------------------------------
__global__ void bias_kernel(const float* __restrict__ table,
                            const int* __restrict__ rel) {
    int idx = blockIdx.x * 256 + threadIdx.x;      // over 8*2401
    if (idx < NH * NTOK * NTOK) {
        int h  = idx / (NTOK * NTOK);
        int nm = idx - h * (NTOK * NTOK);
        g_bias[idx] = table[rel[nm] * NH + h];
    }
}

// ---------------------------------------------------------------------------
// GEMM: out[m][o] = sum_k A[m][k] * W[o][k] + bias[o]
// Tile 128(M) x 64(O) x 16(K). 256 threads, each owns 8x4 outputs held as
// 8x2 f32x2 accumulators. A tile stored in smem as duplicated float2 so the
// f32x2 broadcast operand is a plain 128b smem load.
// MODE 0: A = param (x), scatter epilogue to g_qkv[3][B][H][N][hd]
// MODE 1: A = g_att,     plain epilogue to out[m*256+o]
// ---------------------------------------------------------------------------
template <int MODE>
__global__ __launch_bounds__(256)
void gemm128x64(const float* __restrict__ Ain, const float* __restrict__ W,
                const float* __restrict__ bias, float* __restrict__ out) {
    __shared__ float2 As[2][16][128];   // 32 KB (dup pairs)
    __shared__ float  Bs[2][16][64];    // 8 KB

    const float* A = (MODE == 1) ? (const float*)g_att : Ain;

    const int  tid = threadIdx.x;
    const int  tx  = tid & 15;          // M micro-tile group (0..15)
    const int  ty  = tid >> 4;          // O micro-tile group (0..15)
    const long m0  = (long)blockIdx.x * 128;
    const int  o0  = blockIdx.y * 64;

    // A loader: 2 float4 per thread (128 rows x 16 cols)
    const int ar0 = tid >> 2;           // 0..63
    const int ac0 = (tid & 3) * 4;      // 0,4,8,12
    const int ar1 = ar0 + 64;
    // B loader: 1 float4 per thread (64 rows x 16 cols)
    const int br = tid >> 2;
    const int bc = (tid & 3) * 4;

    const float* Arow0 = A + (m0 + ar0) * 256;
    const float* Arow1 = A + (m0 + ar1) * 256;
    const float* Wrow  = W + (long)(o0 + br) * 256;

    // ---- load K-chunk 0 ----
    {
        float4 a0 = *(const float4*)(Arow0 + ac0);
        float4 a1 = *(const float4*)(Arow1 + ac0);
        float4 b  = *(const float4*)(Wrow + bc);
        As[0][ac0 + 0][ar0] = make_float2(a0.x, a0.x);
        As[0][ac0 + 1][ar0] = make_float2(a0.y, a0.y);
        As[0][ac0 + 2][ar0] = make_float2(a0.z, a0.z);
        As[0][ac0 + 3][ar0] = make_float2(a0.w, a0.w);
        As[0][ac0 + 0][ar1] = make_float2(a1.x, a1.x);
        As[0][ac0 + 1][ar1] = make_float2(a1.y, a1.y);
        As[0][ac0 + 2][ar1] = make_float2(a1.z, a1.z);
        As[0][ac0 + 3][ar1] = make_float2(a1.w, a1.w);
        Bs[0][bc + 0][br] = b.x;
        Bs[0][bc + 1][br] = b.y;
        Bs[0][bc + 2][br] = b.z;
        Bs[0][bc + 3][br] = b.w;
    }
    __syncthreads();

    u64 acc[8][2];
#pragma unroll
    for (int i = 0; i < 8; ++i) { acc[i][0] = 0ull; acc[i][1] = 0ull; }

#pragma unroll 1
    for (int kc = 0; kc < 16; ++kc) {
        const int cur = kc & 1;

        // register-prefetch next K-chunk
        float4 pa0, pa1, pb;
        if (kc < 15) {
            const int kb = (kc + 1) * 16;
            pa0 = *(const float4*)(Arow0 + kb + ac0);
            pa1 = *(const float4*)(Arow1 + kb + ac0);
            pb  = *(const float4*)(Wrow + kb + bc);
        }

#pragma unroll
        for (int kk = 0; kk < 16; ++kk) {
            const u64* ap = (const u64*)&As[cur][kk][tx * 8];
            const u64* bp = (const u64*)&Bs[cur][kk][ty * 4];
            u64 b0 = bp[0], b1 = bp[1];
#pragma unroll
            for (int i = 0; i < 8; ++i) {
                u64 a = ap[i];
                acc[i][0] = f2fma(a, b0, acc[i][0]);
                acc[i][1] = f2fma(a, b1, acc[i][1]);
            }
        }

        if (kc < 15) {
            const int nxt = cur ^ 1;
            As[nxt][ac0 + 0][ar0] = make_float2(pa0.x, pa0.x);
            As[nxt][ac0 + 1][ar0] = make_float2(pa0.y, pa0.y);
            As[nxt][ac0 + 2][ar0] = make_float2(pa0.z, pa0.z);
            As[nxt][ac0 + 3][ar0] = make_float2(pa0.w, pa0.w);
            As[nxt][ac0 + 0][ar1] = make_float2(pa1.x, pa1.x);
            As[nxt][ac0 + 1][ar1] = make_float2(pa1.y, pa1.y);
            As[nxt][ac0 + 2][ar1] = make_float2(pa1.z, pa1.z);
            As[nxt][ac0 + 3][ar1] = make_float2(pa1.w, pa1.w);
            Bs[nxt][bc + 0][br] = pb.x;
            Bs[nxt][bc + 1][br] = pb.y;
            Bs[nxt][bc + 2][br] = pb.z;
            Bs[nxt][bc + 3][br] = pb.w;
        }
        __syncthreads();
    }

    // ---- epilogue ----
#pragma unroll
    for (int i = 0; i < 8; ++i) {
        const long m = m0 + tx * 8 + i;
        int bwin = 0, n = 0;
        if (MODE == 0) { bwin = (int)(m / NTOK); n = (int)(m - (long)bwin * NTOK); }
#pragma unroll
        for (int j = 0; j < 2; ++j) {
            const int o = o0 + ty * 4 + j * 2;
            float v0 = __uint_as_float((unsigned)(acc[i][j] & 0xffffffffull)) + bias[o];
            float v1 = __uint_as_float((unsigned)(acc[i][j] >> 32)) + bias[o + 1];
            if (MODE == 0) {
                // scatter into [which][B][H][N][hd]
#pragma unroll
                for (int l = 0; l < 2; ++l) {
                    const int oo = o + l;
                    const int which = oo >> 8;
                    const int head  = (oo >> 5) & 7;
                    const int d     = oo & 31;
                    const size_t dst = (size_t)which * QKV_S +
                        ((((size_t)bwin * NH + head) * NTOK + n) * HD) + d;
                    g_qkv[dst] = (l == 0) ? v0 : v1;
                }
            } else {
                out[m * 256 + o]     = v0;
                out[m * 256 + o + 1] = v1;
            }
        }
    }
}

// ---------------------------------------------------------------------------
// Kernel 2: fused window attention, one CTA per (window, head)
// ---------------------------------------------------------------------------
__global__ __launch_bounds__(256)
void attn_kernel() {
    __shared__ float sq[NTOK][33], sk[NTOK][33], sv[NTOK][33];
    __shared__ float s[NTOK][NTOK];

    const int tid  = threadIdx.x;
    const int bh   = blockIdx.x;            // b*8 + h
    const int bwin = bh >> 3;
    const int h    = bh & 7;

    const size_t base = (size_t)bh * NTOK * HD;
    const float* gq = g_qkv + base;
    const float* gk = g_qkv + (size_t)QKV_S + base;
    const float* gv = g_qkv + 2ULL * QKV_S + base;

    for (int idx = tid; idx < NTOK * HD; idx += 256) {
        const int r = idx >> 5, c = idx & 31;
        sq[r][c] = gq[idx];
        sk[r][c] = gk[idx];
        sv[r][c] = gv[idx];
    }
    __syncthreads();

    const float scale = 0.17677669529663687f;   // 32^-0.5
    const float* bb = g_bias + h * (NTOK * NTOK);

    for (int idx = tid; idx < NTOK * NTOK; idx += 256) {
        const int n = idx / NTOK;
        const int m = idx - n * NTOK;
        float sum = 0.f;
#pragma unroll
        for (int kk = 0; kk < HD; ++kk) sum += sq[n][kk] * sk[m][kk];
        s[n][m] = sum * scale + bb[idx];
    }
    __syncthreads();

    if (tid < NTOK) {
        float mx = -1e30f;
#pragma unroll
        for (int c = 0; c < NTOK; ++c) mx = fmaxf(mx, s[tid][c]);
        float sum = 0.f;
#pragma unroll
        for (int c = 0; c < NTOK; ++c) {
            float e = __expf(s[tid][c] - mx);
            s[tid][c] = e;
            sum += e;
        }
        const float inv = 1.f / sum;
#pragma unroll
        for (int c = 0; c < NTOK; ++c) s[tid][c] *= inv;
    }
    __syncthreads();

    float* dst = g_att + (size_t)bwin * NTOK * DIM + h * HD;
    for (int idx = tid; idx < NTOK * HD; idx += 256) {
        const int n = idx >> 5, d = idx & 31;
        float sum = 0.f;
#pragma unroll
        for (int m = 0; m < NTOK; ++m) sum += s[n][m] * sv[m][d];
        dst[(size_t)n * DIM + d] = sum;
    }
}

// ---------------------------------------------------------------------------
extern "C" void kernel_launch(void* const* d_in, const int* in_sizes, int n_in,
                              void* d_out, int out_size) {
    const float* x      = (const float*)d_in[0];
    const float* qkv_w  = (const float*)d_in[1];
    const float* qkv_b  = (const float*)d_in[2];
    const float* proj_w = (const float*)d_in[3];
    const float* proj_b = (const float*)d_in[4];
    const float* table  = (const float*)d_in[5];
    const int*   rel    = (const int*)d_in[6];
    float* out = (float*)d_out;

    const int M = BWIN * NTOK;   // 200704, divisible by 128

    bias_kernel<<<(NH * NTOK * NTOK + 255) / 256, 256>>>(table, rel);
    gemm128x64<0><<<dim3(M / 128, 768 / 64), 256>>>(x, qkv_w, qkv_b, nullptr);
    attn_kernel<<<BWIN * NH, 256>>>();
    gemm128x64<1><<<dim3(M / 128, 256 / 64), 256>>>(nullptr, proj_w, proj_b, out);
}

// round 3
// speedup vs baseline: 7.7724x; 7.7724x over previous
#include <cuda_runtime.h>
#include <cuda_bf16.h>
#include <cstdint>

#define BWIN 4096
#define NTOK 49
#define DIM  256
#define NH   8
#define HD   32
#define MTOT (BWIN * NTOK)            /* 200704 */
#define QKV_S (BWIN * NH * NTOK * HD) /* 51380224 */

typedef unsigned long long u64;
typedef unsigned int u32;

// ---------------- device scratch (allocation-free) ----------------
__device__ float g_qkv[3ULL * QKV_S];                       // fp32 [3][B][H][N][hd]
__device__ float g_bias[NH * NTOK * NTOK];                  // [H][N][N]
__device__ __align__(16) __nv_bfloat16 g_xhi[(size_t)MTOT * DIM];
__device__ __align__(16) __nv_bfloat16 g_xlo[(size_t)MTOT * DIM];
__device__ __align__(16) __nv_bfloat16 g_ahi[(size_t)MTOT * DIM];
__device__ __align__(16) __nv_bfloat16 g_alo[(size_t)MTOT * DIM];
__device__ __align__(16) __nv_bfloat16 g_wqhi[768 * 256], g_wqlo[768 * 256];
__device__ __align__(16) __nv_bfloat16 g_wphi[256 * 256], g_wplo[256 * 256];

// ---------------- helpers ----------------
__device__ __forceinline__ u64 f2fma(u64 a, u64 b, u64 c) {
    u64 d;
    asm("fma.rn.f32x2 %0, %1, %2, %3;" : "=l"(d) : "l"(a), "l"(b), "l"(c));
    return d;
}
__device__ __forceinline__ u64 dup32(float x) {
    u64 d;
    asm("mov.b64 %0, {%1, %1};" : "=l"(d) : "r"(__float_as_uint(x)));
    return d;
}
__device__ __forceinline__ void split_bf(float x, unsigned short& h, unsigned short& l) {
    __nv_bfloat16 hb = __float2bfloat16(x);
    float r = x - __bfloat162float(hb);
    __nv_bfloat16 lb = __float2bfloat16(r);
    h = __bfloat16_as_ushort(hb);
    l = __bfloat16_as_ushort(lb);
}

__device__ __forceinline__ void mma16816(float* d, u32 a0, u32 a1, u32 a2, u32 a3,
                                         u32 b0, u32 b1) {
    asm volatile(
        "mma.sync.aligned.m16n8k16.row.col.f32.bf16.bf16.f32 "
        "{%0,%1,%2,%3}, {%4,%5,%6,%7}, {%8,%9}, {%0,%1,%2,%3};"
        : "+f"(d[0]), "+f"(d[1]), "+f"(d[2]), "+f"(d[3])
        : "r"(a0), "r"(a1), "r"(a2), "r"(a3), "r"(b0), "r"(b1));
}

// ---------------- kernel: bias gather ----------------
__global__ void bias_kernel(const float* __restrict__ table, const int* __restrict__ rel) {
    int idx = blockIdx.x * 256 + threadIdx.x;
    if (idx < NH * NTOK * NTOK) {
        int h = idx / (NTOK * NTOK);
        int nm = idx - h * (NTOK * NTOK);
        g_bias[idx] = table[rel[nm] * NH + h];
    }
}

// ---------------- kernels: fp32 -> bf16 hi/lo ----------------
__global__ void conv_x(const float* __restrict__ x) {
    size_t i = (size_t)blockIdx.x * 256 + threadIdx.x;
    if (i < (size_t)MTOT * DIM / 4) {
        float4 v = ((const float4*)x)[i];
        unsigned short h0, h1, h2, h3, l0, l1, l2, l3;
        split_bf(v.x, h0, l0); split_bf(v.y, h1, l1);
        split_bf(v.z, h2, l2); split_bf(v.w, h3, l3);
        ((uint2*)g_xhi)[i] = make_uint2((u32)h0 | ((u32)h1 << 16), (u32)h2 | ((u32)h3 << 16));
        ((uint2*)g_xlo)[i] = make_uint2((u32)l0 | ((u32)l1 << 16), (u32)l2 | ((u32)l3 << 16));
    }
}
__global__ void conv_w(const float* __restrict__ w, int n4, int which) {
    int i = blockIdx.x * 256 + threadIdx.x;
    if (i < n4) {
        __nv_bfloat16* hi = which ? g_wphi : g_wqhi;
        __nv_bfloat16* lo = which ? g_wplo : g_wqlo;
        float4 v = ((const float4*)w)[i];
        unsigned short h0, h1, h2, h3, l0, l1, l2, l3;
        split_bf(v.x, h0, l0); split_bf(v.y, h1, l1);
        split_bf(v.z, h2, l2); split_bf(v.w, h3, l3);
        ((uint2*)hi)[i] = make_uint2((u32)h0 | ((u32)h1 << 16), (u32)h2 | ((u32)h3 << 16));
        ((uint2*)lo)[i] = make_uint2((u32)l0 | ((u32)l1 << 16), (u32)l2 | ((u32)l3 << 16));
    }
}

// ---------------- tensor-core GEMM via mma.sync (bf16 hi/lo, fp32 acc) ----------------
// CTA 128x128, K=256 in 8 chunks of 32, double-buffered smem.
// Row stride 40 bf16 (80 B = 20 words) -> all fragment LDS conflict-free.
#define KC      32
#define RSTRIDE 40
#define TILE_E  (128 * RSTRIDE)            /* bf16 elems per tile */
#define STAGE_E (4 * TILE_E)               /* Ah, Al, Bh, Bl */
#define SMEM_BYTES (2 * STAGE_E * 2)       /* 81920 */

template <int MODE>
__global__ __launch_bounds__(256)
void gemm_mma(const float* __restrict__ bias, float* __restrict__ out) {
    extern __shared__ __nv_bfloat16 sm[];

    const __nv_bfloat16* Ah = MODE ? g_ahi : g_xhi;
    const __nv_bfloat16* Al = MODE ? g_alo : g_xlo;
    const __nv_bfloat16* Bh = MODE ? g_wphi : g_wqhi;
    const __nv_bfloat16* Bl = MODE ? g_wplo : g_wqlo;

    const int tid  = threadIdx.x;
    const int warp = tid >> 5;
    const int lane = tid & 31;
    const int g    = lane >> 2;       // group 0..7
    const int t4   = lane & 3;        // 0..3
    const int wm   = warp >> 2;       // 0..1
    const int wn   = warp & 3;        // 0..3

    const size_t m0 = (size_t)blockIdx.x * 128;
    const int    o0 = blockIdx.y * 128;

    // gmem<->smem copy mapping: 2 uint4 per tile per thread
    const int row0 = tid >> 2;                 // 0..63
    const int row1 = row0 + 64;
    const int seg  = (tid & 3) * 8;            // k offset within chunk

    const __nv_bfloat16* gA0h = Ah + (m0 + row0) * 256 + seg;
    const __nv_bfloat16* gA1h = Ah + (m0 + row1) * 256 + seg;
    const __nv_bfloat16* gA0l = Al + (m0 + row0) * 256 + seg;
    const __nv_bfloat16* gA1l = Al + (m0 + row1) * 256 + seg;
    const __nv_bfloat16* gB0h = Bh + (size_t)(o0 + row0) * 256 + seg;
    const __nv_bfloat16* gB1h = Bh + (size_t)(o0 + row1) * 256 + seg;
    const __nv_bfloat16* gB0l = Bl + (size_t)(o0 + row0) * 256 + seg;
    const __nv_bfloat16* gB1l = Bl + (size_t)(o0 + row1) * 256 + seg;

    const int s0 = row0 * RSTRIDE + seg;
    const int s1 = row1 * RSTRIDE + seg;

    float acc[4][4][4];
#pragma unroll
    for (int a = 0; a < 4; ++a)
#pragma unroll
        for (int b = 0; b < 4; ++b)
#pragma unroll
            for (int c = 0; c < 4; ++c) acc[a][b][c] = 0.f;

    // ---- load chunk 0 into stage 0 ----
    {
        __nv_bfloat16* st = sm;
        *(uint4*)(st + 0 * TILE_E + s0) = *(const uint4*)gA0h;
        *(uint4*)(st + 0 * TILE_E + s1) = *(const uint4*)gA1h;
        *(uint4*)(st + 1 * TILE_E + s0) = *(const uint4*)gA0l;
        *(uint4*)(st + 1 * TILE_E + s1) = *(const uint4*)gA1l;
        *(uint4*)(st + 2 * TILE_E + s0) = *(const uint4*)gB0h;
        *(uint4*)(st + 2 * TILE_E + s1) = *(const uint4*)gB1h;
        *(uint4*)(st + 3 * TILE_E + s0) = *(const uint4*)gB0l;
        *(uint4*)(st + 3 * TILE_E + s1) = *(const uint4*)gB1l;
    }
    __syncthreads();

#pragma unroll 1
    for (int kc = 0; kc < 8; ++kc) {
        const int cur = kc & 1;
        const __nv_bfloat16* st = sm + cur * STAGE_E;

        // prefetch next chunk (gmem -> regs)
        uint4 p[8];
        if (kc < 7) {
            const int kb = (kc + 1) * KC;
            p[0] = *(const uint4*)(gA0h + kb);
            p[1] = *(const uint4*)(gA1h + kb);
            p[2] = *(const uint4*)(gA0l + kb);
            p[3] = *(const uint4*)(gA1l + kb);
            p[4] = *(const uint4*)(gB0h + kb);
            p[5] = *(const uint4*)(gB1h + kb);
            p[6] = *(const uint4*)(gB0l + kb);
            p[7] = *(const uint4*)(gB1l + kb);
        }

        const __nv_bfloat16* sAh = st + 0 * TILE_E + (size_t)(wm * 64) * RSTRIDE;
        const __nv_bfloat16* sAl = st + 1 * TILE_E + (size_t)(wm * 64) * RSTRIDE;
        const __nv_bfloat16* sBh = st + 2 * TILE_E + (size_t)(wn * 32) * RSTRIDE;
        const __nv_bfloat16* sBl = st + 3 * TILE_E + (size_t)(wn * 32) * RSTRIDE;

#pragma unroll
        for (int ks = 0; ks < 2; ++ks) {
            const int k0 = ks * 16 + 2 * t4;
            // B fragments (hi & lo) for 4 n-tiles
            u32 bh0[4], bh1[4], bl0[4], bl1[4];
#pragma unroll
            for (int ni = 0; ni < 4; ++ni) {
                const int br = ni * 8 + g;
                bh0[ni] = *(const u32*)(sBh + br * RSTRIDE + k0);
                bh1[ni] = *(const u32*)(sBh + br * RSTRIDE + k0 + 8);
                bl0[ni] = *(const u32*)(sBl + br * RSTRIDE + k0);
                bl1[ni] = *(const u32*)(sBl + br * RSTRIDE + k0 + 8);
            }
#pragma unroll
            for (int mi = 0; mi < 4; ++mi) {
                const int ar0 = mi * 16 + g;
                const int ar1 = ar0 + 8;
                u32 ah0 = *(const u32*)(sAh + ar0 * RSTRIDE + k0);
                u32 ah1 = *(const u32*)(sAh + ar1 * RSTRIDE + k0);
                u32 ah2 = *(const u32*)(sAh + ar0 * RSTRIDE + k0 + 8);
                u32 ah3 = *(const u32*)(sAh + ar1 * RSTRIDE + k0 + 8);
                u32 al0 = *(const u32*)(sAl + ar0 * RSTRIDE + k0);
                u32 al1 = *(const u32*)(sAl + ar1 * RSTRIDE + k0);
                u32 al2 = *(const u32*)(sAl + ar0 * RSTRIDE + k0 + 8);
                u32 al3 = *(const u32*)(sAl + ar1 * RSTRIDE + k0 + 8);
#pragma unroll
                for (int ni = 0; ni < 4; ++ni) {
                    mma16816(acc[mi][ni], ah0, ah1, ah2, ah3, bh0[ni], bh1[ni]);
                    mma16816(acc[mi][ni], al0, al1, al2, al3, bh0[ni], bh1[ni]);
                    mma16816(acc[mi][ni], ah0, ah1, ah2, ah3, bl0[ni], bl1[ni]);
                }
            }
        }

        if (kc < 7) {
            __nv_bfloat16* nx = sm + (cur ^ 1) * STAGE_E;
            *(uint4*)(nx + 0 * TILE_E + s0) = p[0];
            *(uint4*)(nx + 0 * TILE_E + s1) = p[1];
            *(uint4*)(nx + 1 * TILE_E + s0) = p[2];
            *(uint4*)(nx + 1 * TILE_E + s1) = p[3];
            *(uint4*)(nx + 2 * TILE_E + s0) = p[4];
            *(uint4*)(nx + 2 * TILE_E + s1) = p[5];
            *(uint4*)(nx + 3 * TILE_E + s0) = p[6];
            *(uint4*)(nx + 3 * TILE_E + s1) = p[7];
        }
        __syncthreads();
    }

    // ---- epilogue: bias add + store straight from registers ----
#pragma unroll
    for (int mi = 0; mi < 4; ++mi) {
        const int r0 = (int)m0 + wm * 64 + mi * 16 + g;
        const int r1 = r0 + 8;
#pragma unroll
        for (int ni = 0; ni < 4; ++ni) {
            const int c = o0 + wn * 32 + ni * 8 + 2 * t4;
            const float b0 = bias[c], b1 = bias[c + 1];
            float v00 = acc[mi][ni][0] + b0, v01 = acc[mi][ni][1] + b1;
            float v10 = acc[mi][ni][2] + b0, v11 = acc[mi][ni][3] + b1;
            if (MODE == 0) {
                const int which = c >> 8;
                const int head  = (c >> 5) & 7;
                const int d     = c & 31;
#pragma unroll
                for (int rr = 0; rr < 2; ++rr) {
                    const int m = rr ? r1 : r0;
                    const int bwin = m / NTOK;
                    const int n = m - bwin * NTOK;
                    float* dst = g_qkv + (size_t)which * QKV_S +
                        (((size_t)bwin * NH + head) * NTOK + n) * HD + d;
                    *(float2*)dst = rr ? make_float2(v10, v11) : make_float2(v00, v01);
                }
            } else {
                *(float2*)(out + (size_t)r0 * 256 + c) = make_float2(v00, v01);
                *(float2*)(out + (size_t)r1 * 256 + c) = make_float2(v10, v11);
            }
        }
    }
}

// ---------------- fused window attention (f32x2 register tiles) ----------------
__global__ __launch_bounds__(64)
void attn_kernel() {
    __shared__ __align__(16) float sq[NTOK][34], sk[NTOK][34], sv[NTOK][34];
    __shared__ float s[NTOK][50];

    const int tid = threadIdx.x;
    const int bh = blockIdx.x;
    const int bwin = bh >> 3;
    const int h = bh & 7;

    const size_t base = (size_t)bh * (NTOK * HD);
    const float4* q4 = (const float4*)(g_qkv + base);
    const float4* k4 = (const float4*)(g_qkv + (size_t)QKV_S + base);
    const float4* v4 = (const float4*)(g_qkv + 2ULL * QKV_S + base);

    for (int i = tid; i < NTOK * HD / 4; i += 64) {
        const int r = i >> 3, c = (i & 7) * 4;
        float4 a = q4[i];
        sq[r][c] = a.x; sq[r][c + 1] = a.y; sq[r][c + 2] = a.z; sq[r][c + 3] = a.w;
        float4 b = k4[i];
        sk[r][c] = b.x; sk[r][c + 1] = b.y; sk[r][c + 2] = b.z; sk[r][c + 3] = b.w;
        float4 d = v4[i];
        sv[r][c] = d.x; sv[r][c + 1] = d.y; sv[r][c + 2] = d.z; sv[r][c + 3] = d.w;
    }
    __syncthreads();

    if (tid < 49) {
        const int ti = tid / 7, tj = tid - ti * 7;
        const int n0 = ti * 7, m0 = tj * 7;
        u64 acc[7][7];
#pragma unroll
        for (int r = 0; r < 7; ++r)
#pragma unroll
            for (int cc = 0; cc < 7; ++cc) acc[r][cc] = 0ull;
#pragma unroll
        for (int kk = 0; kk < 16; ++kk) {
            u64 qv[7], kv[7];
#pragma unroll
            for (int r = 0; r < 7; ++r) qv[r] = *(const u64*)&sq[n0 + r][2 * kk];
#pragma unroll
            for (int cc = 0; cc < 7; ++cc) kv[cc] = *(const u64*)&sk[m0 + cc][2 * kk];
#pragma unroll
            for (int r = 0; r < 7; ++r)
#pragma unroll
                for (int cc = 0; cc < 7; ++cc) acc[r][cc] = f2fma(qv[r], kv[cc], acc[r][cc]);
        }
        const float scale = 0.17677669529663687f;
        const float* bb = g_bias + h * (NTOK * NTOK);
#pragma unroll
        for (int r = 0; r < 7; ++r)
#pragma unroll
            for (int cc = 0; cc < 7; ++cc) {
                const u64 a = acc[r][cc];
                const float lo = __uint_as_float((u32)(a & 0xffffffffull));
                const float hi = __uint_as_float((u32)(a >> 32));
                s[n0 + r][m0 + cc] = (lo + hi) * scale + bb[(n0 + r) * NTOK + m0 + cc];
            }
    }
    __syncthreads();

    if (tid < 49) {
        float mx = -1e30f;
#pragma unroll
        for (int c = 0; c < NTOK; ++c) mx = fmaxf(mx, s[tid][c]);
        float sum = 0.f;
#pragma unroll
        for (int c = 0; c < NTOK; ++c) {
            float e = __expf(s[tid][c] - mx);
            s[tid][c] = e;
            sum += e;
        }
        const float inv = 1.f / sum;
#pragma unroll
        for (int c = 0; c < NTOK; ++c) s[tid][c] *= inv;
    }
    __syncthreads();

    if (tid < 28) {
        const int ti = tid >> 2, tj = tid & 3;
        const int n0 = ti * 7, d0 = tj * 8;
        u64 acc2[7][4];
#pragma unroll
        for (int r = 0; r < 7; ++r)
#pragma unroll
            for (int cc = 0; cc < 4; ++cc) acc2[r][cc] = 0ull;
#pragma unroll 7
        for (int m = 0; m < NTOK; ++m) {
            u64 vv[4];
#pragma unroll
            for (int cc = 0; cc < 4; ++cc) vv[cc] = *(const u64*)&sv[m][d0 + 2 * cc];
#pragma unroll
            for (int r = 0; r < 7; ++r) {
                const u64 sd = dup32(s[n0 + r][m]);
#pragma unroll
                for (int cc = 0; cc < 4; ++cc) acc2[r][cc] = f2fma(sd, vv[cc], acc2[r][cc]);
            }
        }
#pragma unroll
        for (int r = 0; r < 7; ++r) {
            unsigned short hh[8], ll[8];
#pragma unroll
            for (int cc = 0; cc < 4; ++cc) {
                const u64 a = acc2[r][cc];
                split_bf(__uint_as_float((u32)(a & 0xffffffffull)), hh[2 * cc], ll[2 * cc]);
                split_bf(__uint_as_float((u32)(a >> 32)), hh[2 * cc + 1], ll[2 * cc + 1]);
            }
            uint4 vh = make_uint4((u32)hh[0] | ((u32)hh[1] << 16), (u32)hh[2] | ((u32)hh[3] << 16),
                                  (u32)hh[4] | ((u32)hh[5] << 16), (u32)hh[6] | ((u32)hh[7] << 16));
            uint4 vl = make_uint4((u32)ll[0] | ((u32)ll[1] << 16), (u32)ll[2] | ((u32)ll[3] << 16),
                                  (u32)ll[4] | ((u32)ll[5] << 16), (u32)ll[6] | ((u32)ll[7] << 16));
            const size_t off = ((size_t)bwin * NTOK + n0 + r) * 256 + h * 32 + d0;
            *(uint4*)(g_ahi + off) = vh;
            *(uint4*)(g_alo + off) = vl;
        }
    }
}

// ---------------- launch ----------------
extern "C" void kernel_launch(void* const* d_in, const int* in_sizes, int n_in,
                              void* d_out, int out_size) {
    const float* x      = (const float*)d_in[0];
    const float* qkv_w  = (const float*)d_in[1];
    const float* qkv_b  = (const float*)d_in[2];
    const float* proj_w = (const float*)d_in[3];
    const float* proj_b = (const float*)d_in[4];
    const float* table  = (const float*)d_in[5];
    const int*   rel    = (const int*)d_in[6];
    float* out = (float*)d_out;

    static int smem_set = 0;
    if (!smem_set) {
        cudaFuncSetAttribute(gemm_mma<0>, cudaFuncAttributeMaxDynamicSharedMemorySize, SMEM_BYTES);
        cudaFuncSetAttribute(gemm_mma<1>, cudaFuncAttributeMaxDynamicSharedMemorySize, SMEM_BYTES);
        smem_set = 1;
    }

    bias_kernel<<<(NH * NTOK * NTOK + 255) / 256, 256>>>(table, rel);
    conv_x<<<(int)(((size_t)MTOT * DIM / 4 + 255) / 256), 256>>>(x);
    conv_w<<<(768 * 256 / 4 + 255) / 256, 256>>>(qkv_w, 768 * 256 / 4, 0);
    conv_w<<<(256 * 256 / 4 + 255) / 256, 256>>>(proj_w, 256 * 256 / 4, 1);
    gemm_mma<0><<<dim3(MTOT / 128, 6), 256, SMEM_BYTES>>>(qkv_b, nullptr);
    attn_kernel<<<BWIN * NH, 64>>>();
    gemm_mma<1><<<dim3(MTOT / 128, 2), 256, SMEM_BYTES>>>(proj_b, out);
}

// round 4
// speedup vs baseline: 9.6527x; 1.2419x over previous
#include <cuda_runtime.h>
#include <cuda_bf16.h>
#include <cstdint>

#define BWIN 4096
#define NTOK 49
#define DIM  256
#define NH   8
#define HD   32
#define MTOT (BWIN * NTOK)            /* 200704 */
#define QKV_S (BWIN * NH * NTOK * HD) /* 51380224 */

typedef unsigned long long u64;
typedef unsigned int u32;

// ---------------- device scratch (allocation-free) ----------------
__device__ float g_qkv[3ULL * QKV_S];                       // fp32 [3][B][H][N][hd]
__device__ float g_bias[NH * NTOK * NTOK];                  // [H][N][N]
__device__ __align__(16) __nv_bfloat16 g_xhi[(size_t)MTOT * DIM];
__device__ __align__(16) __nv_bfloat16 g_xlo[(size_t)MTOT * DIM];
__device__ __align__(16) __nv_bfloat16 g_ahi[(size_t)MTOT * DIM];
__device__ __align__(16) __nv_bfloat16 g_alo[(size_t)MTOT * DIM];
__device__ __align__(16) __nv_bfloat16 g_wqhi[768 * 256], g_wqlo[768 * 256];
__device__ __align__(16) __nv_bfloat16 g_wphi[256 * 256], g_wplo[256 * 256];

// ---------------- helpers ----------------
__device__ __forceinline__ u64 f2fma(u64 a, u64 b, u64 c) {
    u64 d;
    asm("fma.rn.f32x2 %0, %1, %2, %3;" : "=l"(d) : "l"(a), "l"(b), "l"(c));
    return d;
}
__device__ __forceinline__ u64 dup32(float x) {
    u64 d;
    asm("mov.b64 %0, {%1, %1};" : "=l"(d) : "r"(__float_as_uint(x)));
    return d;
}
__device__ __forceinline__ void split_bf(float x, unsigned short& h, unsigned short& l) {
    __nv_bfloat16 hb = __float2bfloat16(x);
    float r = x - __bfloat162float(hb);
    __nv_bfloat16 lb = __float2bfloat16(r);
    h = __bfloat16_as_ushort(hb);
    l = __bfloat16_as_ushort(lb);
}
__device__ __forceinline__ u32 smem_u32(const void* p) {
    u32 a;
    asm("{ .reg .u64 t; cvta.to.shared.u64 t, %1; cvt.u32.u64 %0, t; }" : "=r"(a) : "l"(p));
    return a;
}

__device__ __forceinline__ void mma16816(float* d, u32 a0, u32 a1, u32 a2, u32 a3,
                                         u32 b0, u32 b1) {
    asm volatile(
        "mma.sync.aligned.m16n8k16.row.col.f32.bf16.bf16.f32 "
        "{%0,%1,%2,%3}, {%4,%5,%6,%7}, {%8,%9}, {%0,%1,%2,%3};"
        : "+f"(d[0]), "+f"(d[1]), "+f"(d[2]), "+f"(d[3])
        : "r"(a0), "r"(a1), "r"(a2), "r"(a3), "r"(b0), "r"(b1));
}

#define LDSM_X4(r0, r1, r2, r3, addr) \
    asm volatile("ldmatrix.sync.aligned.m8n8.x4.shared.b16 {%0,%1,%2,%3}, [%4];" \
        : "=r"(r0), "=r"(r1), "=r"(r2), "=r"(r3) : "r"(addr))

#define CP_ASYNC16(s, g) \
    asm volatile("cp.async.cg.shared.global [%0], [%1], 16;" :: "r"(s), "l"(g))
#define CP_COMMIT() asm volatile("cp.async.commit_group;" ::: "memory")
#define CP_WAIT0()  asm volatile("cp.async.wait_group 0;" ::: "memory")

// ---------------- kernel: bias gather ----------------
__global__ void bias_kernel(const float* __restrict__ table, const int* __restrict__ rel) {
    int idx = blockIdx.x * 256 + threadIdx.x;
    if (idx < NH * NTOK * NTOK) {
        int h = idx / (NTOK * NTOK);
        int nm = idx - h * (NTOK * NTOK);
        g_bias[idx] = table[rel[nm] * NH + h];
    }
}

// ---------------- kernels: fp32 -> bf16 hi/lo ----------------
__global__ void conv_x(const float* __restrict__ x) {
    size_t i = (size_t)blockIdx.x * 256 + threadIdx.x;
    if (i < (size_t)MTOT * DIM / 4) {
        float4 v = ((const float4*)x)[i];
        unsigned short h0, h1, h2, h3, l0, l1, l2, l3;
        split_bf(v.x, h0, l0); split_bf(v.y, h1, l1);
        split_bf(v.z, h2, l2); split_bf(v.w, h3, l3);
        ((uint2*)g_xhi)[i] = make_uint2((u32)h0 | ((u32)h1 << 16), (u32)h2 | ((u32)h3 << 16));
        ((uint2*)g_xlo)[i] = make_uint2((u32)l0 | ((u32)l1 << 16), (u32)l2 | ((u32)l3 << 16));
    }
}
__global__ void conv_w(const float* __restrict__ w, int n4, int which) {
    int i = blockIdx.x * 256 + threadIdx.x;
    if (i < n4) {
        __nv_bfloat16* hi = which ? g_wphi : g_wqhi;
        __nv_bfloat16* lo = which ? g_wplo : g_wqlo;
        float4 v = ((const float4*)w)[i];
        unsigned short h0, h1, h2, h3, l0, l1, l2, l3;
        split_bf(v.x, h0, l0); split_bf(v.y, h1, l1);
        split_bf(v.z, h2, l2); split_bf(v.w, h3, l3);
        ((uint2*)hi)[i] = make_uint2((u32)h0 | ((u32)h1 << 16), (u32)h2 | ((u32)h3 << 16));
        ((uint2*)lo)[i] = make_uint2((u32)l0 | ((u32)l1 << 16), (u32)l2 | ((u32)l3 << 16));
    }
}

// ---------------- tensor-core GEMM (bf16 hi/lo, fp32 acc, ldmatrix + cp.async) ----
#define KC      32
#define RSTRIDE 40                          /* elements; 80B rows, conflict-free */
#define TILE_E  (128 * RSTRIDE)
#define TILE_B  (TILE_E * 2)
#define STAGE_B (4 * TILE_B)                /* Ah, Al, Bh, Bl = 40960 B */
#define SMEM_BYTES (2 * STAGE_B)            /* 81920 */

template <int MODE>
__global__ __launch_bounds__(256)
void gemm_mma(const float* __restrict__ bias, float* __restrict__ out) {
    extern __shared__ __nv_bfloat16 sm[];

    const __nv_bfloat16* Ah = MODE ? g_ahi : g_xhi;
    const __nv_bfloat16* Al = MODE ? g_alo : g_xlo;
    const __nv_bfloat16* Bh = MODE ? g_wphi : g_wqhi;
    const __nv_bfloat16* Bl = MODE ? g_wplo : g_wqlo;

    const int tid  = threadIdx.x;
    const int warp = tid >> 5;
    const int lane = tid & 31;
    const int g    = lane >> 2;
    const int t4   = lane & 3;
    const int wm   = warp >> 2;       // 0..1
    const int wn   = warp & 3;        // 0..3

    // N-block fastest (blockIdx.x) -> concurrent CTAs share A slice in L2
    const int    o0 = blockIdx.x * 128;
    const size_t m0 = (size_t)blockIdx.y * 128;

    const u32 smem_base = smem_u32(sm);

    // gmem -> smem copy mapping: 2 x 16B per tile per thread
    const int row0 = tid >> 2;
    const int row1 = row0 + 64;
    const int seg  = (tid & 3) * 8;

    const __nv_bfloat16* gA0h = Ah + (m0 + row0) * 256 + seg;
    const __nv_bfloat16* gA1h = Ah + (m0 + row1) * 256 + seg;
    const __nv_bfloat16* gA0l = Al + (m0 + row0) * 256 + seg;
    const __nv_bfloat16* gA1l = Al + (m0 + row1) * 256 + seg;
    const __nv_bfloat16* gB0h = Bh + (size_t)(o0 + row0) * 256 + seg;
    const __nv_bfloat16* gB1h = Bh + (size_t)(o0 + row1) * 256 + seg;
    const __nv_bfloat16* gB0l = Bl + (size_t)(o0 + row0) * 256 + seg;
    const __nv_bfloat16* gB1l = Bl + (size_t)(o0 + row1) * 256 + seg;

    const u32 s0b = (u32)(row0 * RSTRIDE + seg) * 2;
    const u32 s1b = (u32)(row1 * RSTRIDE + seg) * 2;

    // ldmatrix per-lane offsets (bytes, relative to stage base)
    const int q3 = (lane >> 3) & 1;
    const int q4 = (lane >> 4) & 1;
    const int r8 = lane & 7;
    const u32 offA  = 0 * TILE_B + (u32)(((wm * 64 + q3 * 8 + r8) * RSTRIDE) + q4 * 8) * 2;
    const u32 offB0 = 2 * TILE_B + (u32)(((wn * 32 + 0 * 16 + q4 * 8 + r8) * RSTRIDE) + q3 * 8) * 2;
    const u32 offB1 = 2 * TILE_B + (u32)(((wn * 32 + 1 * 16 + q4 * 8 + r8) * RSTRIDE) + q3 * 8) * 2;

    float acc[4][4][4];
#pragma unroll
    for (int a = 0; a < 4; ++a)
#pragma unroll
        for (int b = 0; b < 4; ++b)
#pragma unroll
            for (int c = 0; c < 4; ++c) acc[a][b][c] = 0.f;

    // ---- prologue: cp.async chunk 0 into stage 0 ----
    {
        const u32 st = smem_base;
        CP_ASYNC16(st + 0 * TILE_B + s0b, gA0h);
        CP_ASYNC16(st + 0 * TILE_B + s1b, gA1h);
        CP_ASYNC16(st + 1 * TILE_B + s0b, gA0l);
        CP_ASYNC16(st + 1 * TILE_B + s1b, gA1l);
        CP_ASYNC16(st + 2 * TILE_B + s0b, gB0h);
        CP_ASYNC16(st + 2 * TILE_B + s1b, gB1h);
        CP_ASYNC16(st + 3 * TILE_B + s0b, gB0l);
        CP_ASYNC16(st + 3 * TILE_B + s1b, gB1l);
        CP_COMMIT();
        CP_WAIT0();
    }
    __syncthreads();

#pragma unroll 1
    for (int kc = 0; kc < 8; ++kc) {
        const int cur = kc & 1;
        const u32 stb = smem_base + cur * STAGE_B;

        if (kc < 7) {
            const int kb = (kc + 1) * KC;
            const u32 nx = smem_base + (cur ^ 1) * STAGE_B;
            CP_ASYNC16(nx + 0 * TILE_B + s0b, gA0h + kb);
            CP_ASYNC16(nx + 0 * TILE_B + s1b, gA1h + kb);
            CP_ASYNC16(nx + 1 * TILE_B + s0b, gA0l + kb);
            CP_ASYNC16(nx + 1 * TILE_B + s1b, gA1l + kb);
            CP_ASYNC16(nx + 2 * TILE_B + s0b, gB0h + kb);
            CP_ASYNC16(nx + 2 * TILE_B + s1b, gB1h + kb);
            CP_ASYNC16(nx + 3 * TILE_B + s0b, gB0l + kb);
            CP_ASYNC16(nx + 3 * TILE_B + s1b, gB1l + kb);
            CP_COMMIT();
        }

#pragma unroll
        for (int ks = 0; ks < 2; ++ks) {
            const u32 kso = (u32)(ks * 32);
            u32 bh[4][2], bl[4][2];
            LDSM_X4(bh[0][0], bh[0][1], bh[1][0], bh[1][1], stb + offB0 + kso);
            LDSM_X4(bh[2][0], bh[2][1], bh[3][0], bh[3][1], stb + offB1 + kso);
            LDSM_X4(bl[0][0], bl[0][1], bl[1][0], bl[1][1], stb + offB0 + TILE_B + kso);
            LDSM_X4(bl[2][0], bl[2][1], bl[3][0], bl[3][1], stb + offB1 + TILE_B + kso);
#pragma unroll
            for (int mi = 0; mi < 4; ++mi) {
                const u32 ao = stb + offA + (u32)(mi * 16 * RSTRIDE * 2) + kso;
                u32 ah0, ah1, ah2, ah3, al0, al1, al2, al3;
                LDSM_X4(ah0, ah1, ah2, ah3, ao);
                LDSM_X4(al0, al1, al2, al3, ao + TILE_B);
#pragma unroll
                for (int ni = 0; ni < 4; ++ni) {
                    mma16816(acc[mi][ni], ah0, ah1, ah2, ah3, bh[ni][0], bh[ni][1]);
                    mma16816(acc[mi][ni], al0, al1, al2, al3, bh[ni][0], bh[ni][1]);
                    mma16816(acc[mi][ni], ah0, ah1, ah2, ah3, bl[ni][0], bl[ni][1]);
                }
            }
        }

        if (kc < 7) CP_WAIT0();
        __syncthreads();
    }

    // ---- epilogue: bias add + store straight from registers ----
#pragma unroll
    for (int mi = 0; mi < 4; ++mi) {
        const int r0 = (int)m0 + wm * 64 + mi * 16 + g;
        const int r1 = r0 + 8;
#pragma unroll
        for (int ni = 0; ni < 4; ++ni) {
            const int c = o0 + wn * 32 + ni * 8 + 2 * t4;
            const float b0 = bias[c], b1 = bias[c + 1];
            float v00 = acc[mi][ni][0] + b0, v01 = acc[mi][ni][1] + b1;
            float v10 = acc[mi][ni][2] + b0, v11 = acc[mi][ni][3] + b1;
            if (MODE == 0) {
                const int which = c >> 8;
                const int head  = (c >> 5) & 7;
                const int d     = c & 31;
#pragma unroll
                for (int rr = 0; rr < 2; ++rr) {
                    const int m = rr ? r1 : r0;
                    const int bwin = m / NTOK;
                    const int n = m - bwin * NTOK;
                    float* dst = g_qkv + (size_t)which * QKV_S +
                        (((size_t)bwin * NH + head) * NTOK + n) * HD + d;
                    *(float2*)dst = rr ? make_float2(v10, v11) : make_float2(v00, v01);
                }
            } else {
                *(float2*)(out + (size_t)r0 * 256 + c) = make_float2(v00, v01);
                *(float2*)(out + (size_t)r1 * 256 + c) = make_float2(v10, v11);
            }
        }
    }
}

// ---------------- fused window attention (f32x2 register tiles) ----------------
__global__ __launch_bounds__(64)
void attn_kernel() {
    __shared__ __align__(16) float sq[NTOK][34], sk[NTOK][34], sv[NTOK][34];
    __shared__ float s[NTOK][50];

    const int tid = threadIdx.x;
    const int bh = blockIdx.x;
    const int bwin = bh >> 3;
    const int h = bh & 7;

    const size_t base = (size_t)bh * (NTOK * HD);
    const float4* q4 = (const float4*)(g_qkv + base);
    const float4* k4 = (const float4*)(g_qkv + (size_t)QKV_S + base);
    const float4* v4 = (const float4*)(g_qkv + 2ULL * QKV_S + base);

    for (int i = tid; i < NTOK * HD / 4; i += 64) {
        const int r = i >> 3, c = (i & 7) * 4;
        float4 a = q4[i];
        sq[r][c] = a.x; sq[r][c + 1] = a.y; sq[r][c + 2] = a.z; sq[r][c + 3] = a.w;
        float4 b = k4[i];
        sk[r][c] = b.x; sk[r][c + 1] = b.y; sk[r][c + 2] = b.z; sk[r][c + 3] = b.w;
        float4 d = v4[i];
        sv[r][c] = d.x; sv[r][c + 1] = d.y; sv[r][c + 2] = d.z; sv[r][c + 3] = d.w;
    }
    __syncthreads();

    if (tid < 49) {
        const int ti = tid / 7, tj = tid - ti * 7;
        const int n0 = ti * 7, m0 = tj * 7;
        u64 acc[7][7];
#pragma unroll
        for (int r = 0; r < 7; ++r)
#pragma unroll
            for (int cc = 0; cc < 7; ++cc) acc[r][cc] = 0ull;
#pragma unroll
        for (int kk = 0; kk < 16; ++kk) {
            u64 qv[7], kv[7];
#pragma unroll
            for (int r = 0; r < 7; ++r) qv[r] = *(const u64*)&sq[n0 + r][2 * kk];
#pragma unroll
            for (int cc = 0; cc < 7; ++cc) kv[cc] = *(const u64*)&sk[m0 + cc][2 * kk];
#pragma unroll
            for (int r = 0; r < 7; ++r)
#pragma unroll
                for (int cc = 0; cc < 7; ++cc) acc[r][cc] = f2fma(qv[r], kv[cc], acc[r][cc]);
        }
        const float scale = 0.17677669529663687f;
        const float* bb = g_bias + h * (NTOK * NTOK);
#pragma unroll
        for (int r = 0; r < 7; ++r)
#pragma unroll
            for (int cc = 0; cc < 7; ++cc) {
                const u64 a = acc[r][cc];
                const float lo = __uint_as_float((u32)(a & 0xffffffffull));
                const float hi = __uint_as_float((u32)(a >> 32));
                s[n0 + r][m0 + cc] = (lo + hi) * scale + bb[(n0 + r) * NTOK + m0 + cc];
            }
    }
    __syncthreads();

    if (tid < 49) {
        float mx = -1e30f;
#pragma unroll
        for (int c = 0; c < NTOK; ++c) mx = fmaxf(mx, s[tid][c]);
        float sum = 0.f;
#pragma unroll
        for (int c = 0; c < NTOK; ++c) {
            float e = __expf(s[tid][c] - mx);
            s[tid][c] = e;
            sum += e;
        }
        const float inv = 1.f / sum;
#pragma unroll
        for (int c = 0; c < NTOK; ++c) s[tid][c] *= inv;
    }
    __syncthreads();

    if (tid < 28) {
        const int ti = tid >> 2, tj = tid & 3;
        const int n0 = ti * 7, d0 = tj * 8;
        u64 acc2[7][4];
#pragma unroll
        for (int r = 0; r < 7; ++r)
#pragma unroll
            for (int cc = 0; cc < 4; ++cc) acc2[r][cc] = 0ull;
#pragma unroll 7
        for (int m = 0; m < NTOK; ++m) {
            u64 vv[4];
#pragma unroll
            for (int cc = 0; cc < 4; ++cc) vv[cc] = *(const u64*)&sv[m][d0 + 2 * cc];
#pragma unroll
            for (int r = 0; r < 7; ++r) {
                const u64 sd = dup32(s[n0 + r][m]);
#pragma unroll
                for (int cc = 0; cc < 4; ++cc) acc2[r][cc] = f2fma(sd, vv[cc], acc2[r][cc]);
            }
        }
#pragma unroll
        for (int r = 0; r < 7; ++r) {
            unsigned short hh[8], ll[8];
#pragma unroll
            for (int cc = 0; cc < 4; ++cc) {
                const u64 a = acc2[r][cc];
                split_bf(__uint_as_float((u32)(a & 0xffffffffull)), hh[2 * cc], ll[2 * cc]);
                split_bf(__uint_as_float((u32)(a >> 32)), hh[2 * cc + 1], ll[2 * cc + 1]);
            }
            uint4 vh = make_uint4((u32)hh[0] | ((u32)hh[1] << 16), (u32)hh[2] | ((u32)hh[3] << 16),
                                  (u32)hh[4] | ((u32)hh[5] << 16), (u32)hh[6] | ((u32)hh[7] << 16));
            uint4 vl = make_uint4((u32)ll[0] | ((u32)ll[1] << 16), (u32)ll[2] | ((u32)ll[3] << 16),
                                  (u32)ll[4] | ((u32)ll[5] << 16), (u32)ll[6] | ((u32)ll[7] << 16));
            const size_t off = ((size_t)bwin * NTOK + n0 + r) * 256 + h * 32 + d0;
            *(uint4*)(g_ahi + off) = vh;
            *(uint4*)(g_alo + off) = vl;
        }
    }
}

// ---------------- launch ----------------
extern "C" void kernel_launch(void* const* d_in, const int* in_sizes, int n_in,
                              void* d_out, int out_size) {
    const float* x      = (const float*)d_in[0];
    const float* qkv_w  = (const float*)d_in[1];
    const float* qkv_b  = (const float*)d_in[2];
    const float* proj_w = (const float*)d_in[3];
    const float* proj_b = (const float*)d_in[4];
    const float* table  = (const float*)d_in[5];
    const int*   rel    = (const int*)d_in[6];
    float* out = (float*)d_out;

    static int smem_set = 0;
    if (!smem_set) {
        cudaFuncSetAttribute(gemm_mma<0>, cudaFuncAttributeMaxDynamicSharedMemorySize, SMEM_BYTES);
        cudaFuncSetAttribute(gemm_mma<1>, cudaFuncAttributeMaxDynamicSharedMemorySize, SMEM_BYTES);
        smem_set = 1;
    }

    bias_kernel<<<(NH * NTOK * NTOK + 255) / 256, 256>>>(table, rel);
    conv_x<<<(int)(((size_t)MTOT * DIM / 4 + 255) / 256), 256>>>(x);
    conv_w<<<(768 * 256 / 4 + 255) / 256, 256>>>(qkv_w, 768 * 256 / 4, 0);
    conv_w<<<(256 * 256 / 4 + 255) / 256, 256>>>(proj_w, 256 * 256 / 4, 1);
    gemm_mma<0><<<dim3(6, MTOT / 128), 256, SMEM_BYTES>>>(qkv_b, nullptr);
    attn_kernel<<<BWIN * NH, 64>>>();
    gemm_mma<1><<<dim3(2, MTOT / 128), 256, SMEM_BYTES>>>(proj_b, out);
}